// round 7
// baseline (speedup 1.0000x reference)
#include <cuda_runtime.h>
#include <cstdint>
#include <cstddef>

// Neural-CDE forward, R7: 256 CTAs x 256 threads, 2 CTAs/SM (occupancy 2) so
// one CTA's GEMM compute hides the other CTA's barrier/reduction bubbles
// (R6 evidence: issue 43%, fma 49% -> SM half-idle at barriers with 1 CTA).
// Per CTA: MC=4 batch rows, 8-way split-K (group == warp), 8 weight cols per
// thread. Same packed fma.rn.f32x2 core, fully unrolled, act LDS pipelined.

#define T_N   128
#define IN_N  32
#define H_N   256
#define OUT_N 32
#define MC    4            // batch rows per CTA
#define BST   4            // activation buffer stride [dim][row]
#define NTH   256
#define NG    8            // split-K groups (one warp each)
#define NCT   32           // column-threads per group (8 cols each)
#define KSH   (H_N / NG)   // 32
#define KSI   (IN_N / NG)  // 4
#define RST   36           // reduction stride in floats (32 data + 4 pad)

#define BUF_FLOATS   (H_N * BST)            // 1024
#define RED_FLOATS   (NG * NCT * RST)       // 9216
#define SCR_FLOATS   128                    // projection partial scratch
#define SMEM_FLOATS  (2 * BUF_FLOATS + RED_FLOATS + SCR_FLOATS)
#define SMEM_BYTES   (SMEM_FLOATS * 4)      // 45,568

typedef unsigned long long u64;

__device__ __forceinline__ u64 fma2(u64 a, u64 b, u64 c) {
    u64 d;
    asm("fma.rn.f32x2 %0, %1, %2, %3;" : "=l"(d) : "l"(a), "l"(b), "l"(c));
    return d;
}
__device__ __forceinline__ u64 dup2(float x) {
    u64 d; unsigned int u = __float_as_uint(x);
    asm("mov.b64 %0, {%1, %2};" : "=l"(d) : "r"(u), "r"(u));
    return d;
}
__device__ __forceinline__ float lipswish(float x) {
    return 0.909f * x / (1.0f + __expf(-x));
}

// Raw partial GEMM over k in [koff, koff+KS), 8 columns n0..n0+7, 4 rows.
// acc[c*2+p] packs rows (2p,2p+1) of column n0+c.  W row-major [*][H_N];
// buf [dim][row] stride BST (broadcast LDS.128 per k-row).  Fully unrolled;
// act load pipelined 1 k-row ahead; weights prefetched 2 blocks (4 k-rows).
template <int KS>
__device__ __forceinline__ void gemmT8(const float* __restrict__ W,
                                       const float* __restrict__ buf,
                                       int n0, int koff,
                                       u64* __restrict__ acc)
{
#pragma unroll
    for (int i = 0; i < 16; i++) acc[i] = 0ull;
    const float* Wp = W + (size_t)koff * H_N + n0;
    const float* bp = buf + koff * BST;

    // weight block = 2 k-rows x 8 cols = 4 float4
    float4 wA[4], wB[4];
    wA[0] = *(const float4*)(Wp);                       wA[1] = *(const float4*)(Wp + 4);
    wA[2] = *(const float4*)(Wp + H_N);                 wA[3] = *(const float4*)(Wp + H_N + 4);
    {
        const int k2 = 2 & (KS - 1), k3 = 3 & (KS - 1);
        wB[0] = *(const float4*)(Wp + k2 * H_N);        wB[1] = *(const float4*)(Wp + k2 * H_N + 4);
        wB[2] = *(const float4*)(Wp + k3 * H_N);        wB[3] = *(const float4*)(Wp + k3 * H_N + 4);
    }

    ulonglong2 ua = *(const ulonglong2*)(bp);   // rows (0,1),(2,3) of k-row 0

#pragma unroll
    for (int kb = 0; kb < KS; kb += 2) {
        const int kn0 = (kb + 4) & (KS - 1);    // wrap: dead reload on tail
        const int kn1 = (kb + 5) & (KS - 1);
        float4 wN[4];
        wN[0] = *(const float4*)(Wp + kn0 * H_N);   wN[1] = *(const float4*)(Wp + kn0 * H_N + 4);
        wN[2] = *(const float4*)(Wp + kn1 * H_N);   wN[3] = *(const float4*)(Wp + kn1 * H_N + 4);
#pragma unroll
        for (int j = 0; j < 2; j++) {
            const int knext = (kb + j + 1) & (KS - 1);        // pipelined act load
            ulonglong2 na = *(const ulonglong2*)(bp + knext * BST);
            const float4 wv0 = wA[j * 2], wv1 = wA[j * 2 + 1];
            u64 w0 = dup2(wv0.x), w1 = dup2(wv0.y), w2 = dup2(wv0.z), w3 = dup2(wv0.w);
            u64 w4 = dup2(wv1.x), w5 = dup2(wv1.y), w6 = dup2(wv1.z), w7 = dup2(wv1.w);
            acc[0]  = fma2(ua.x, w0, acc[0]);   acc[1]  = fma2(ua.y, w0, acc[1]);
            acc[2]  = fma2(ua.x, w1, acc[2]);   acc[3]  = fma2(ua.y, w1, acc[3]);
            acc[4]  = fma2(ua.x, w2, acc[4]);   acc[5]  = fma2(ua.y, w2, acc[5]);
            acc[6]  = fma2(ua.x, w3, acc[6]);   acc[7]  = fma2(ua.y, w3, acc[7]);
            acc[8]  = fma2(ua.x, w4, acc[8]);   acc[9]  = fma2(ua.y, w4, acc[9]);
            acc[10] = fma2(ua.x, w5, acc[10]);  acc[11] = fma2(ua.y, w5, acc[11]);
            acc[12] = fma2(ua.x, w6, acc[12]);  acc[13] = fma2(ua.y, w6, acc[13]);
            acc[14] = fma2(ua.x, w7, acc[14]);  acc[15] = fma2(ua.y, w7, acc[15]);
            ua = na;
        }
#pragma unroll
        for (int j = 0; j < 4; j++) { wA[j] = wB[j]; wB[j] = wN[j]; }
    }
}

// Deposit 32 raw floats: word layout c*4 + m  (c=0..7 local col, m=0..3 row).
__device__ __forceinline__ void red_put(float* __restrict__ redp,
                                        const u64* __restrict__ acc)
{
#pragma unroll
    for (int c = 0; c < 8; c++)
        *(ulonglong2*)(redp + c * 4) = make_ulonglong2(acc[c * 2], acc[c * 2 + 1]);
}

// Sum the 8 group-partials for this thread's column (4 rows, LDS.128 each).
__device__ __forceinline__ float4 combine8(const float* __restrict__ red,
                                           int owner, int off)
{
    const float* p = red + owner * RST + off;
    float4 s = *(const float4*)(p);
#pragma unroll
    for (int g = 1; g < NG; g++) {
        float4 v = *(const float4*)(p + g * NCT * RST);
        s.x += v.x; s.y += v.y; s.z += v.z; s.w += v.w;
    }
    return s;
}

// Projection partial: s = [bd[c] +] sum_{k in half} buf[k][r] * Wd[k][c].
__device__ __forceinline__ float proj_part(const float* __restrict__ buf,
                                           const float* __restrict__ Wd,
                                           const float* __restrict__ bd,
                                           int kh, int r, int c)
{
    float s = (kh == 0) ? bd[c] : 0.f;
    const int k0 = kh * (H_N / 2);
#pragma unroll 8
    for (int kk = k0; kk < k0 + H_N / 2; kk++)
        s = fmaf(buf[kk * BST + r], Wd[kk * OUT_N + c], s);
    return s;
}

__global__ void __launch_bounds__(NTH, 2)
cde_kernel(const float* __restrict__ coeffs, const float* __restrict__ times,
           const float* __restrict__ Wi,     const float* __restrict__ bi,
           const float* __restrict__ Wf,     const float* __restrict__ bfb,
           const float* __restrict__ Wd,     const float* __restrict__ bd,
           float* __restrict__ out)
{
    extern __shared__ float smem[];
    float* bufA = smem;                                  // 1024 floats
    float* bufB = smem + BUF_FLOATS;                     // 1024 floats
    float* red  = smem + 2 * BUF_FLOATS;                 // 9216 floats
    float* scr  = smem + 2 * BUF_FLOATS + RED_FLOATS;    // 128 floats

    const int tid   = threadIdx.x;
    const int kg    = tid >> 5;                 // split-K group 0..7 (== warp)
    const int ct    = tid & 31;                 // column-thread in group
    const int n0    = ct * 8;
    const int bbase = blockIdx.x * MC;

    // combine/update mapping: thread owns column n_e, all 4 rows
    const int n_e   = tid;                      // column 0..255
    const int owner = tid >> 3;                 // ct of depositing thread
    const int off   = (tid & 7) * 4;            // local col * 4

    // projection mapping: 128 outputs x 2 K-halves
    const int p_id = tid & 127;
    const int p_kh = tid >> 7;
    const int p_r  = p_id >> 5;                 // batch row 0..3
    const int p_c  = p_id & 31;                 // output column

    float* redp = red + (kg * NCT + ct) * RST;
    u64 acc[16];

    // ---- stage coeffs[:,0,:] -> bufA[k][m] ----
    if (tid < 128) {
        int m = tid >> 5, kk = tid & 31;
        bufA[kk * BST + m] = coeffs[(size_t)(bbase + m) * T_N * IN_N + kk];
    }
    __syncthreads();

    // ---- y0 = coeffs0 @ Wi + bi ----
    float y[4], ksum[4];
    gemmT8<KSI>(Wi, bufA, n0, kg * KSI, acc);
    red_put(redp, acc);
    __syncthreads();
    {
        float4 v = combine8(red, owner, off);
        float bb = bi[n_e];
        y[0] = v.x + bb; y[1] = v.y + bb; y[2] = v.z + bb; y[3] = v.w + bb;
        *(float4*)(bufA + n_e * BST) = make_float4(y[0], y[1], y[2], y[3]);
    }
    __syncthreads();

    // ---- time loop; proj of y_t folded into stage-0/layer-0 of step t ----
#pragma unroll 1
    for (int t = 0; t < T_N - 1; t++) {
        const float dt = times[t + 1] - times[t];

#pragma unroll 1
        for (int st = 0; st < 4; st++) {
            float* in = bufA; float* ob = bufB;
            float ps = 0.f;
#pragma unroll 1
            for (int l = 0; l < 3; l++) {
                if (st == 0 && l == 0) {
                    // projection partial of y_t (bufA stable through this GEMM)
                    ps = proj_part(bufA, Wd, bd, p_kh, p_r, p_c);
                    if (p_kh) scr[p_id] = ps;
                }
                gemmT8<KSH>(Wf + (size_t)l * H_N * H_N, in, n0, kg * KSH, acc);
                red_put(redp, acc);
                __syncthreads();     // covers red partials (+ scr on st0/l0)
                if (st == 0 && l == 0 && !p_kh)
                    out[((size_t)(bbase + p_r) * T_N + t) * OUT_N + p_c] = ps + scr[p_id];
                float4 v = combine8(red, owner, off);
                float bb = bfb[l * H_N + n_e];
                v.x = lipswish(v.x + bb); v.y = lipswish(v.y + bb);
                v.z = lipswish(v.z + bb); v.w = lipswish(v.w + bb);
                *(float4*)(ob + n_e * BST) = v;
                __syncthreads();
                float* tmp = in; in = ob; ob = tmp;
            }
            gemmT8<KSH>(Wf + (size_t)3 * H_N * H_N, in, n0, kg * KSH, acc);
            red_put(redp, acc);
            __syncthreads();
            float4 kv = combine8(red, owner, off);
            {
                float bb = bfb[3 * H_N + n_e];
                kv.x += bb; kv.y += bb; kv.z += bb; kv.w += bb;
            }
            float k4[4] = {kv.x, kv.y, kv.z, kv.w};
            float s4[4];
            if (st == 0) {
#pragma unroll
                for (int i = 0; i < 4; i++) { ksum[i] = k4[i]; s4[i] = fmaf(0.5f * dt, k4[i], y[i]); }
            } else if (st == 1) {
#pragma unroll
                for (int i = 0; i < 4; i++) { ksum[i] = fmaf(2.f, k4[i], ksum[i]); s4[i] = fmaf(0.5f * dt, k4[i], y[i]); }
            } else if (st == 2) {
#pragma unroll
                for (int i = 0; i < 4; i++) { ksum[i] = fmaf(2.f, k4[i], ksum[i]); s4[i] = fmaf(dt, k4[i], y[i]); }
            } else {
#pragma unroll
                for (int i = 0; i < 4; i++) { ksum[i] += k4[i]; y[i] = fmaf(dt * (1.f / 6.f), ksum[i], y[i]); s4[i] = y[i]; }
            }
            *(float4*)(bufA + n_e * BST) = make_float4(s4[0], s4[1], s4[2], s4[3]);
            __syncthreads();
        }
    }

    // ---- final projection of y_{T-1} ----
    {
        float ps = proj_part(bufA, Wd, bd, p_kh, p_r, p_c);
        if (p_kh) scr[p_id] = ps;
        __syncthreads();
        if (!p_kh)
            out[((size_t)(bbase + p_r) * T_N + (T_N - 1)) * OUT_N + p_c] = ps + scr[p_id];
    }
}

extern "C" void kernel_launch(void* const* d_in, const int* in_sizes, int n_in,
                              void* d_out, int out_size)
{
    const float* coeffs = (const float*)d_in[0];
    const float* times  = (const float*)d_in[1];
    const float* Wi     = (const float*)d_in[2];
    const float* bi     = (const float*)d_in[3];
    const float* Wf     = (const float*)d_in[4];
    const float* bf     = (const float*)d_in[5];
    const float* Wd     = (const float*)d_in[6];
    const float* bd     = (const float*)d_in[7];
    float* out = (float*)d_out;

    cudaFuncSetAttribute(cde_kernel,
                         cudaFuncAttributeMaxDynamicSharedMemorySize, SMEM_BYTES);

    const int B    = in_sizes[0] / (T_N * IN_N);   // 1024
    const int grid = B / MC;                       // 256
    cde_kernel<<<grid, NTH, SMEM_BYTES>>>(coeffs, times, Wi, bi, Wf, bf, Wd, bd, out);
}

// round 9
// speedup vs baseline: 1.5716x; 1.5716x over previous
#include <cuda_runtime.h>
#include <cstdint>
#include <cstddef>

// Neural-CDE forward, R9 = R8 design with the acc[14] FMA operand fixed
// (ua.x -> ub.x; the benched R8 ran the uncorrected line and failed).
// Config: 128 CTAs x 512 thr, MC=8, 8-way split-K, 4 cols/thread, plus:
//  (a) exact weight loads (no wrap-around dead LDGs),
//  (b) cross-GEMM weight prefetch issued before the reduction barrier,
//  (c) dead-tail act LDS removed (compile-time guards).

#define T_N   128
#define IN_N  32
#define H_N   256
#define OUT_N 32
#define MC    8            // batch rows per CTA
#define BST   8            // activation buffer stride [dim][row]
#define NTH   512
#define NG    8            // split-K groups
#define NCT   64           // column-threads per group (4 cols each)
#define KSH   (H_N / NG)   // 32
#define KSI   (IN_N / NG)  // 4
#define RST   36           // reduction stride in floats (32 data + 4 pad)

#define BUF_FLOATS   (H_N * BST)            // 2048
#define RED_FLOATS   (NG * NCT * RST)       // 18432
#define SCR_FLOATS   256                    // projection partial scratch
#define SMEM_FLOATS  (2 * BUF_FLOATS + RED_FLOATS + SCR_FLOATS)
#define SMEM_BYTES   (SMEM_FLOATS * 4)      // 91136

typedef unsigned long long u64;

__device__ __forceinline__ u64 fma2(u64 a, u64 b, u64 c) {
    u64 d;
    asm("fma.rn.f32x2 %0, %1, %2, %3;" : "=l"(d) : "l"(a), "l"(b), "l"(c));
    return d;
}
__device__ __forceinline__ u64 dup2(float x) {
    u64 d; unsigned int u = __float_as_uint(x);
    asm("mov.b64 %0, {%1, %2};" : "=l"(d) : "r"(u), "r"(u));
    return d;
}
__device__ __forceinline__ float lipswish(float x) {
    return 0.909f * x / (1.0f + __expf(-x));
}

// Preload the first two 4-k-row weight blocks of a GEMM (guards compile out).
template <int KS>
__device__ __forceinline__ void wpre(const float* __restrict__ Wp,
                                     float4* __restrict__ wA,
                                     float4* __restrict__ wB)
{
#pragma unroll
    for (int j = 0; j < 4; j++) if (j < KS)     wA[j] = *(const float4*)(Wp + j * H_N);
#pragma unroll
    for (int j = 0; j < 4; j++) if (4 + j < KS) wB[j] = *(const float4*)(Wp + (4 + j) * H_N);
}

// Raw partial GEMM over KS k-rows, 4 columns, 8 rows. acc[c*4+p] packs rows
// (2p,2p+1) of local column c: p=0 -> ua.x, p=1 -> ua.y, p=2 -> ub.x,
// p=3 -> ub.y. Wp pre-offset to (koff, n0); bp pre-offset to koff. wA/wB hold
// the first two blocks (preloaded by caller before the previous barrier).
template <int KS>
__device__ __forceinline__ void gemmT4(const float* __restrict__ Wp,
                                       const float* __restrict__ bp,
                                       float4* __restrict__ wA,
                                       float4* __restrict__ wB,
                                       u64* __restrict__ acc)
{
#pragma unroll
    for (int i = 0; i < 16; i++) acc[i] = 0ull;

    ulonglong2 ua = *(const ulonglong2*)(bp);       // k-row 0: rows (0,1),(2,3)
    ulonglong2 ub = *(const ulonglong2*)(bp + 4);   //          rows (4,5),(6,7)

#pragma unroll
    for (int kb = 0; kb < KS; kb += 4) {
        float4 wN[4];
        const bool ldw = (kb + 8 < KS);
        if (ldw) {
#pragma unroll
            for (int j = 0; j < 4; j++) wN[j] = *(const float4*)(Wp + (kb + 8 + j) * H_N);
        }
#pragma unroll
        for (int j = 0; j < 4; j++) {
            if (kb + j >= KS) continue;                    // compile-time (KS=4 case)
            const int knext = kb + j + 1;
            ulonglong2 na, nb;
            const bool lda = (knext < KS);
            if (lda) {
                na = *(const ulonglong2*)(bp + knext * BST);
                nb = *(const ulonglong2*)(bp + knext * BST + 4);
            }
            u64 w0 = dup2(wA[j].x), w1 = dup2(wA[j].y);
            u64 w2 = dup2(wA[j].z), w3 = dup2(wA[j].w);
            acc[0]  = fma2(ua.x, w0, acc[0]);  acc[1]  = fma2(ua.y, w0, acc[1]);
            acc[2]  = fma2(ub.x, w0, acc[2]);  acc[3]  = fma2(ub.y, w0, acc[3]);
            acc[4]  = fma2(ua.x, w1, acc[4]);  acc[5]  = fma2(ua.y, w1, acc[5]);
            acc[6]  = fma2(ub.x, w1, acc[6]);  acc[7]  = fma2(ub.y, w1, acc[7]);
            acc[8]  = fma2(ua.x, w2, acc[8]);  acc[9]  = fma2(ua.y, w2, acc[9]);
            acc[10] = fma2(ub.x, w2, acc[10]); acc[11] = fma2(ub.y, w2, acc[11]);
            acc[12] = fma2(ua.x, w3, acc[12]); acc[13] = fma2(ua.y, w3, acc[13]);
            acc[14] = fma2(ub.x, w3, acc[14]); acc[15] = fma2(ub.y, w3, acc[15]);
            if (lda) { ua = na; ub = nb; }
        }
#pragma unroll
        for (int j = 0; j < 4; j++) wA[j] = wB[j];
        if (ldw) {
#pragma unroll
            for (int j = 0; j < 4; j++) wB[j] = wN[j];
        }
    }
}

// Deposit 32 raw floats (16 packed pairs) at redp: word layout c*8+m.
__device__ __forceinline__ void red_put(float* __restrict__ redp,
                                        const u64* __restrict__ acc)
{
#pragma unroll
    for (int c = 0; c < 4; c++) {
        *(ulonglong2*)(redp + c * 8)     = make_ulonglong2(acc[c * 4],     acc[c * 4 + 1]);
        *(ulonglong2*)(redp + c * 8 + 4) = make_ulonglong2(acc[c * 4 + 2], acc[c * 4 + 3]);
    }
}

// Sum the 8 group-partials for this thread's float4 (conflict-free LDS.128).
__device__ __forceinline__ float4 combine8(const float* __restrict__ red,
                                           int ct_e, int off)
{
    const float* p = red + ct_e * RST + off;
    float4 s = *(const float4*)(p);
#pragma unroll
    for (int g = 1; g < NG; g++) {
        float4 v = *(const float4*)(p + g * NCT * RST);
        s.x += v.x; s.y += v.y; s.z += v.z; s.w += v.w;
    }
    return s;
}

// Projection partial: s = [bd[c] +] sum_{k in half} buf[k][r] * Wd[k][c].
__device__ __forceinline__ float proj_part(const float* __restrict__ buf,
                                           const float* __restrict__ Wd,
                                           const float* __restrict__ bd,
                                           int kh, int r, int c)
{
    float s = (kh == 0) ? bd[c] : 0.f;
    const int k0 = kh * (H_N / 2);
#pragma unroll 8
    for (int kk = k0; kk < k0 + H_N / 2; kk++)
        s = fmaf(buf[kk * BST + r], Wd[kk * OUT_N + c], s);
    return s;
}

__global__ void __launch_bounds__(NTH, 1)
cde_kernel(const float* __restrict__ coeffs, const float* __restrict__ times,
           const float* __restrict__ Wi,     const float* __restrict__ bi,
           const float* __restrict__ Wf,     const float* __restrict__ bfb,
           const float* __restrict__ Wd,     const float* __restrict__ bd,
           float* __restrict__ out)
{
    extern __shared__ float smem[];
    float* bufA = smem;                                  // 2048 floats
    float* bufB = smem + BUF_FLOATS;                     // 2048 floats
    float* red  = smem + 2 * BUF_FLOATS;                 // 18432 floats
    float* scr  = smem + 2 * BUF_FLOATS + RED_FLOATS;    // 256 floats

    const int tid   = threadIdx.x;
    const int kg    = tid >> 6;                 // split-K group 0..7
    const int ct    = tid & 63;                 // column-thread in group
    const int n0    = ct * 4;
    const int bbase = blockIdx.x * MC;

    // combine/update mapping: thread owns column n_e, rows m0..m0+3
    const int ct_e = tid >> 3;
    const int sub  = tid & 7;
    const int c_e  = sub >> 1;
    const int m0   = (sub & 1) * 4;
    const int n_e  = ct_e * 4 + c_e;
    const int off  = c_e * 8 + m0;

    // projection mapping
    const int p_id = tid & 255;
    const int p_kh = tid >> 8;
    const int p_r  = p_id >> 5;
    const int p_c  = p_id & 31;

    float* redp = red + (kg * NCT + ct) * RST;
    u64 acc[16];
    float4 wA[4], wB[4];

    // per-thread weight base for the hidden layers (periodic cycle 0,1,2,3->0)
    const size_t HH = (size_t)H_N * H_N;
    const float* W0 = Wf + (size_t)kg * KSH * H_N + n0;
    const int kact  = kg * KSH * BST;           // act offset for hidden GEMMs

    // ---- stage coeffs[:,0,:] -> bufA[k][m] ----
    if (tid < 256) {
        int m = tid >> 5, kk = tid & 31;
        bufA[kk * BST + m] = coeffs[(size_t)(bbase + m) * T_N * IN_N + kk];
    }

    // preload init-GEMM weights (KSI=4: one block) while staging lands
    wpre<KSI>(Wi + (size_t)kg * KSI * H_N + n0, wA, wB);
    __syncthreads();

    // ---- y0 = coeffs0 @ Wi + bi ----
    float y[4], ksum[4];
    gemmT4<KSI>(Wi + (size_t)kg * KSI * H_N + n0, bufA + kg * KSI * BST, wA, wB, acc);
    red_put(redp, acc);
    wpre<KSH>(W0, wA, wB);                      // prefetch layer-0 weights
    __syncthreads();
    {
        float4 v = combine8(red, ct_e, off);
        float bb = bi[n_e];
        y[0] = v.x + bb; y[1] = v.y + bb; y[2] = v.z + bb; y[3] = v.w + bb;
        *(float4*)(bufA + n_e * BST + m0) = make_float4(y[0], y[1], y[2], y[3]);
    }
    __syncthreads();

    // ---- time loop; proj of y_t folded into stage-0/layer-0 of step t ----
#pragma unroll 1
    for (int t = 0; t < T_N - 1; t++) {
        const float dt = times[t + 1] - times[t];

#pragma unroll 1
        for (int st = 0; st < 4; st++) {
            float* in = bufA; float* ob = bufB;
            float ps = 0.f;
#pragma unroll 1
            for (int l = 0; l < 3; l++) {
                if (st == 0 && l == 0) {
                    // projection partial of y_t (bufA stable through this GEMM)
                    ps = proj_part(bufA, Wd, bd, p_kh, p_r, p_c);
                    if (p_kh) scr[p_id] = ps;
                }
                gemmT4<KSH>(W0 + l * HH, in + kact, wA, wB, acc);
                red_put(redp, acc);
                wpre<KSH>(W0 + (l + 1) * HH, wA, wB);   // prefetch next layer
                __syncthreads();
                if (st == 0 && l == 0 && !p_kh)
                    out[((size_t)(bbase + p_r) * T_N + t) * OUT_N + p_c] = ps + scr[p_id];
                float4 v = combine8(red, ct_e, off);
                float bb = bfb[l * H_N + n_e];
                v.x = lipswish(v.x + bb); v.y = lipswish(v.y + bb);
                v.z = lipswish(v.z + bb); v.w = lipswish(v.w + bb);
                *(float4*)(ob + n_e * BST + m0) = v;
                __syncthreads();
                float* tmp = in; in = ob; ob = tmp;
            }
            gemmT4<KSH>(W0 + 3 * HH, in + kact, wA, wB, acc);
            red_put(redp, acc);
            wpre<KSH>(W0, wA, wB);                      // prefetch next stage L0
            __syncthreads();
            float4 kv = combine8(red, ct_e, off);
            {
                float bb = bfb[3 * H_N + n_e];
                kv.x += bb; kv.y += bb; kv.z += bb; kv.w += bb;
            }
            float k4[4] = {kv.x, kv.y, kv.z, kv.w};
            float s4[4];
            if (st == 0) {
#pragma unroll
                for (int i = 0; i < 4; i++) { ksum[i] = k4[i]; s4[i] = fmaf(0.5f * dt, k4[i], y[i]); }
            } else if (st == 1) {
#pragma unroll
                for (int i = 0; i < 4; i++) { ksum[i] = fmaf(2.f, k4[i], ksum[i]); s4[i] = fmaf(0.5f * dt, k4[i], y[i]); }
            } else if (st == 2) {
#pragma unroll
                for (int i = 0; i < 4; i++) { ksum[i] = fmaf(2.f, k4[i], ksum[i]); s4[i] = fmaf(dt, k4[i], y[i]); }
            } else {
#pragma unroll
                for (int i = 0; i < 4; i++) { ksum[i] += k4[i]; y[i] = fmaf(dt * (1.f / 6.f), ksum[i], y[i]); s4[i] = y[i]; }
            }
            *(float4*)(bufA + n_e * BST + m0) = make_float4(s4[0], s4[1], s4[2], s4[3]);
            __syncthreads();
        }
    }

    // ---- final projection of y_{T-1} ----
    {
        float ps = proj_part(bufA, Wd, bd, p_kh, p_r, p_c);
        if (p_kh) scr[p_id] = ps;
        __syncthreads();
        if (!p_kh)
            out[((size_t)(bbase + p_r) * T_N + (T_N - 1)) * OUT_N + p_c] = ps + scr[p_id];
    }
}

extern "C" void kernel_launch(void* const* d_in, const int* in_sizes, int n_in,
                              void* d_out, int out_size)
{
    const float* coeffs = (const float*)d_in[0];
    const float* times  = (const float*)d_in[1];
    const float* Wi     = (const float*)d_in[2];
    const float* bi     = (const float*)d_in[3];
    const float* Wf     = (const float*)d_in[4];
    const float* bf     = (const float*)d_in[5];
    const float* Wd     = (const float*)d_in[6];
    const float* bd     = (const float*)d_in[7];
    float* out = (float*)d_out;

    cudaFuncSetAttribute(cde_kernel,
                         cudaFuncAttributeMaxDynamicSharedMemorySize, SMEM_BYTES);

    const int B    = in_sizes[0] / (T_N * IN_N);   // 1024
    const int grid = B / MC;                       // 128
    cde_kernel<<<grid, NTH, SMEM_BYTES>>>(coeffs, times, Wi, bi, Wf, bf, Wd, bd, out);
}

// round 10
// speedup vs baseline: 1.5899x; 1.0116x over previous
#include <cuda_runtime.h>
#include <cstdint>
#include <cstddef>

// Neural-CDE forward, R10 = R9 plus:
//  (a) act-ready barriers made GROUP-LOCAL: group kg's next GEMM reads act
//      columns [32kg,32kg+32), written exactly by tids [64kg,64kg+64) = group
//      kg itself -> bar.sync(1+kg, 64) instead of full __syncthreads()
//      (except stage-3 end, where the folded projection reads all columns).
//  (b) loop-invariant bias loads (bfb x4, bd) hoisted to registers off the
//      critical combine path.
// Config unchanged: 128 CTAs x 512 thr, MC=8, 8-way split-K, 4 cols/thread,
// packed fma.rn.f32x2, exact weight loads, cross-GEMM weight prefetch.

#define T_N   128
#define IN_N  32
#define H_N   256
#define OUT_N 32
#define MC    8            // batch rows per CTA
#define BST   8            // activation buffer stride [dim][row]
#define NTH   512
#define NG    8            // split-K groups
#define NCT   64           // column-threads per group (4 cols each)
#define KSH   (H_N / NG)   // 32
#define KSI   (IN_N / NG)  // 4
#define RST   36           // reduction stride in floats (32 data + 4 pad)

#define BUF_FLOATS   (H_N * BST)            // 2048
#define RED_FLOATS   (NG * NCT * RST)       // 18432
#define SCR_FLOATS   256                    // projection partial scratch
#define SMEM_FLOATS  (2 * BUF_FLOATS + RED_FLOATS + SCR_FLOATS)
#define SMEM_BYTES   (SMEM_FLOATS * 4)      // 91136

typedef unsigned long long u64;

__device__ __forceinline__ u64 fma2(u64 a, u64 b, u64 c) {
    u64 d;
    asm("fma.rn.f32x2 %0, %1, %2, %3;" : "=l"(d) : "l"(a), "l"(b), "l"(c));
    return d;
}
__device__ __forceinline__ u64 dup2(float x) {
    u64 d; unsigned int u = __float_as_uint(x);
    asm("mov.b64 %0, {%1, %2};" : "=l"(d) : "r"(u), "r"(u));
    return d;
}
__device__ __forceinline__ float lipswish(float x) {
    return 0.909f * x / (1.0f + __expf(-x));
}
// 64-thread named barrier for split-K group kg (ids 1..8; 0 = __syncthreads).
__device__ __forceinline__ void gbar(int kg) {
    asm volatile("bar.sync %0, %1;" :: "r"(1 + kg), "r"(64) : "memory");
}

// Preload the first two 4-k-row weight blocks of a GEMM (guards compile out).
template <int KS>
__device__ __forceinline__ void wpre(const float* __restrict__ Wp,
                                     float4* __restrict__ wA,
                                     float4* __restrict__ wB)
{
#pragma unroll
    for (int j = 0; j < 4; j++) if (j < KS)     wA[j] = *(const float4*)(Wp + j * H_N);
#pragma unroll
    for (int j = 0; j < 4; j++) if (4 + j < KS) wB[j] = *(const float4*)(Wp + (4 + j) * H_N);
}

// Raw partial GEMM over KS k-rows, 4 columns, 8 rows. acc[c*4+p] packs rows
// (2p,2p+1) of local column c: p=0 -> ua.x, p=1 -> ua.y, p=2 -> ub.x,
// p=3 -> ub.y. Wp pre-offset to (koff, n0); bp pre-offset to koff. wA/wB hold
// the first two blocks (preloaded by caller before the previous barrier).
template <int KS>
__device__ __forceinline__ void gemmT4(const float* __restrict__ Wp,
                                       const float* __restrict__ bp,
                                       float4* __restrict__ wA,
                                       float4* __restrict__ wB,
                                       u64* __restrict__ acc)
{
#pragma unroll
    for (int i = 0; i < 16; i++) acc[i] = 0ull;

    ulonglong2 ua = *(const ulonglong2*)(bp);       // k-row 0: rows (0,1),(2,3)
    ulonglong2 ub = *(const ulonglong2*)(bp + 4);   //          rows (4,5),(6,7)

#pragma unroll
    for (int kb = 0; kb < KS; kb += 4) {
        float4 wN[4];
        const bool ldw = (kb + 8 < KS);
        if (ldw) {
#pragma unroll
            for (int j = 0; j < 4; j++) wN[j] = *(const float4*)(Wp + (kb + 8 + j) * H_N);
        }
#pragma unroll
        for (int j = 0; j < 4; j++) {
            if (kb + j >= KS) continue;                    // compile-time (KS=4 case)
            const int knext = kb + j + 1;
            ulonglong2 na, nb;
            const bool lda = (knext < KS);
            if (lda) {
                na = *(const ulonglong2*)(bp + knext * BST);
                nb = *(const ulonglong2*)(bp + knext * BST + 4);
            }
            u64 w0 = dup2(wA[j].x), w1 = dup2(wA[j].y);
            u64 w2 = dup2(wA[j].z), w3 = dup2(wA[j].w);
            acc[0]  = fma2(ua.x, w0, acc[0]);  acc[1]  = fma2(ua.y, w0, acc[1]);
            acc[2]  = fma2(ub.x, w0, acc[2]);  acc[3]  = fma2(ub.y, w0, acc[3]);
            acc[4]  = fma2(ua.x, w1, acc[4]);  acc[5]  = fma2(ua.y, w1, acc[5]);
            acc[6]  = fma2(ub.x, w1, acc[6]);  acc[7]  = fma2(ub.y, w1, acc[7]);
            acc[8]  = fma2(ua.x, w2, acc[8]);  acc[9]  = fma2(ua.y, w2, acc[9]);
            acc[10] = fma2(ub.x, w2, acc[10]); acc[11] = fma2(ub.y, w2, acc[11]);
            acc[12] = fma2(ua.x, w3, acc[12]); acc[13] = fma2(ua.y, w3, acc[13]);
            acc[14] = fma2(ub.x, w3, acc[14]); acc[15] = fma2(ub.y, w3, acc[15]);
            if (lda) { ua = na; ub = nb; }
        }
#pragma unroll
        for (int j = 0; j < 4; j++) wA[j] = wB[j];
        if (ldw) {
#pragma unroll
            for (int j = 0; j < 4; j++) wB[j] = wN[j];
        }
    }
}

// Deposit 32 raw floats (16 packed pairs) at redp: word layout c*8+m.
__device__ __forceinline__ void red_put(float* __restrict__ redp,
                                        const u64* __restrict__ acc)
{
#pragma unroll
    for (int c = 0; c < 4; c++) {
        *(ulonglong2*)(redp + c * 8)     = make_ulonglong2(acc[c * 4],     acc[c * 4 + 1]);
        *(ulonglong2*)(redp + c * 8 + 4) = make_ulonglong2(acc[c * 4 + 2], acc[c * 4 + 3]);
    }
}

// Sum the 8 group-partials for this thread's float4 (conflict-free LDS.128).
__device__ __forceinline__ float4 combine8(const float* __restrict__ red,
                                           int ct_e, int off)
{
    const float* p = red + ct_e * RST + off;
    float4 s = *(const float4*)(p);
#pragma unroll
    for (int g = 1; g < NG; g++) {
        float4 v = *(const float4*)(p + g * NCT * RST);
        s.x += v.x; s.y += v.y; s.z += v.z; s.w += v.w;
    }
    return s;
}

// Projection partial: s = [bdv +] sum_{k in half} buf[k][r] * Wd[k][c].
__device__ __forceinline__ float proj_part(const float* __restrict__ buf,
                                           const float* __restrict__ Wd,
                                           float bdv,
                                           int kh, int r, int c)
{
    float s = (kh == 0) ? bdv : 0.f;
    const int k0 = kh * (H_N / 2);
#pragma unroll 8
    for (int kk = k0; kk < k0 + H_N / 2; kk++)
        s = fmaf(buf[kk * BST + r], Wd[kk * OUT_N + c], s);
    return s;
}

__global__ void __launch_bounds__(NTH, 1)
cde_kernel(const float* __restrict__ coeffs, const float* __restrict__ times,
           const float* __restrict__ Wi,     const float* __restrict__ bi,
           const float* __restrict__ Wf,     const float* __restrict__ bfb,
           const float* __restrict__ Wd,     const float* __restrict__ bd,
           float* __restrict__ out)
{
    extern __shared__ float smem[];
    float* bufA = smem;                                  // 2048 floats
    float* bufB = smem + BUF_FLOATS;                     // 2048 floats
    float* red  = smem + 2 * BUF_FLOATS;                 // 18432 floats
    float* scr  = smem + 2 * BUF_FLOATS + RED_FLOATS;    // 256 floats

    const int tid   = threadIdx.x;
    const int kg    = tid >> 6;                 // split-K group 0..7
    const int ct    = tid & 63;                 // column-thread in group
    const int n0    = ct * 4;
    const int bbase = blockIdx.x * MC;

    // combine/update mapping: thread owns column n_e, rows m0..m0+3.
    // NOTE: tids [64kg,64kg+64) own columns [32kg,32kg+32) — exactly the
    // k-slice group kg's own GEMM reads -> act-ready sync is group-local.
    const int ct_e = tid >> 3;
    const int sub  = tid & 7;
    const int c_e  = sub >> 1;
    const int m0   = (sub & 1) * 4;
    const int n_e  = ct_e * 4 + c_e;
    const int off  = c_e * 8 + m0;

    // projection mapping
    const int p_id = tid & 255;
    const int p_kh = tid >> 8;
    const int p_r  = p_id >> 5;
    const int p_c  = p_id & 31;

    float* redp = red + (kg * NCT + ct) * RST;
    u64 acc[16];
    float4 wA[4], wB[4];

    // loop-invariant scalars hoisted off the combine critical path
    const float bias0 = bfb[0 * H_N + n_e];
    const float bias1 = bfb[1 * H_N + n_e];
    const float bias2 = bfb[2 * H_N + n_e];
    const float bias3 = bfb[3 * H_N + n_e];
    const float bdv   = bd[p_c];

    // per-thread weight base for the hidden layers
    const size_t HH = (size_t)H_N * H_N;
    const float* W0 = Wf + (size_t)kg * KSH * H_N + n0;
    const int kact  = kg * KSH * BST;           // act offset for hidden GEMMs

    // ---- stage coeffs[:,0,:] -> bufA[k][m] ----
    if (tid < 256) {
        int m = tid >> 5, kk = tid & 31;
        bufA[kk * BST + m] = coeffs[(size_t)(bbase + m) * T_N * IN_N + kk];
    }

    // preload init-GEMM weights (KSI=4: one block) while staging lands
    wpre<KSI>(Wi + (size_t)kg * KSI * H_N + n0, wA, wB);
    __syncthreads();

    // ---- y0 = coeffs0 @ Wi + bi ----
    float y[4], ksum[4];
    gemmT4<KSI>(Wi + (size_t)kg * KSI * H_N + n0, bufA + kg * KSI * BST, wA, wB, acc);
    red_put(redp, acc);
    wpre<KSH>(W0, wA, wB);                      // prefetch layer-0 weights
    __syncthreads();
    {
        float4 v = combine8(red, ct_e, off);
        float bb = bi[n_e];
        y[0] = v.x + bb; y[1] = v.y + bb; y[2] = v.z + bb; y[3] = v.w + bb;
        *(float4*)(bufA + n_e * BST + m0) = make_float4(y[0], y[1], y[2], y[3]);
    }
    __syncthreads();            // full: next proj (st0/l0) reads ALL columns

    // ---- time loop; proj of y_t folded into stage-0/layer-0 of step t ----
#pragma unroll 1
    for (int t = 0; t < T_N - 1; t++) {
        const float dt = times[t + 1] - times[t];

#pragma unroll 1
        for (int st = 0; st < 4; st++) {
            float* in = bufA; float* ob = bufB;
            float ps = 0.f;
#pragma unroll 1
            for (int l = 0; l < 3; l++) {
                if (st == 0 && l == 0) {
                    // projection partial of y_t (bufA stable through this GEMM)
                    ps = proj_part(bufA, Wd, bdv, p_kh, p_r, p_c);
                    if (p_kh) scr[p_id] = ps;
                }
                gemmT4<KSH>(W0 + l * HH, in + kact, wA, wB, acc);
                red_put(redp, acc);
                wpre<KSH>(W0 + (l + 1) * HH, wA, wB);   // prefetch next layer
                __syncthreads();     // full: deposits cross all groups (+scr)
                if (st == 0 && l == 0 && !p_kh)
                    out[((size_t)(bbase + p_r) * T_N + t) * OUT_N + p_c] = ps + scr[p_id];
                float4 v = combine8(red, ct_e, off);
                float bb = (l == 0) ? bias0 : (l == 1) ? bias1 : bias2;
                v.x = lipswish(v.x + bb); v.y = lipswish(v.y + bb);
                v.z = lipswish(v.z + bb); v.w = lipswish(v.w + bb);
                *(float4*)(ob + n_e * BST + m0) = v;
                gbar(kg);            // group-local: own GEMM reads own columns
                float* tmp = in; in = ob; ob = tmp;
            }
            gemmT4<KSH>(W0 + 3 * HH, in + kact, wA, wB, acc);
            red_put(redp, acc);
            wpre<KSH>(W0, wA, wB);                      // prefetch next stage L0
            __syncthreads();         // full: deposits cross all groups
            float4 kv = combine8(red, ct_e, off);
            kv.x += bias3; kv.y += bias3; kv.z += bias3; kv.w += bias3;
            float k4[4] = {kv.x, kv.y, kv.z, kv.w};
            float s4[4];
            if (st == 0) {
#pragma unroll
                for (int i = 0; i < 4; i++) { ksum[i] = k4[i]; s4[i] = fmaf(0.5f * dt, k4[i], y[i]); }
            } else if (st == 1) {
#pragma unroll
                for (int i = 0; i < 4; i++) { ksum[i] = fmaf(2.f, k4[i], ksum[i]); s4[i] = fmaf(0.5f * dt, k4[i], y[i]); }
            } else if (st == 2) {
#pragma unroll
                for (int i = 0; i < 4; i++) { ksum[i] = fmaf(2.f, k4[i], ksum[i]); s4[i] = fmaf(dt, k4[i], y[i]); }
            } else {
#pragma unroll
                for (int i = 0; i < 4; i++) { ksum[i] += k4[i]; y[i] = fmaf(dt * (1.f / 6.f), ksum[i], y[i]); s4[i] = y[i]; }
            }
            *(float4*)(bufA + n_e * BST + m0) = make_float4(s4[0], s4[1], s4[2], s4[3]);
            if (st < 3) gbar(kg);    // group-local: next stage L0 reads own cols
            else        __syncthreads();   // full: st0/l0 proj reads ALL columns
        }
    }

    // ---- final projection of y_{T-1} ----
    {
        float ps = proj_part(bufA, Wd, bdv, p_kh, p_r, p_c);
        if (p_kh) scr[p_id] = ps;
        __syncthreads();
        if (!p_kh)
            out[((size_t)(bbase + p_r) * T_N + (T_N - 1)) * OUT_N + p_c] = ps + scr[p_id];
    }
}

extern "C" void kernel_launch(void* const* d_in, const int* in_sizes, int n_in,
                              void* d_out, int out_size)
{
    const float* coeffs = (const float*)d_in[0];
    const float* times  = (const float*)d_in[1];
    const float* Wi     = (const float*)d_in[2];
    const float* bi     = (const float*)d_in[3];
    const float* Wf     = (const float*)d_in[4];
    const float* bf     = (const float*)d_in[5];
    const float* Wd     = (const float*)d_in[6];
    const float* bd     = (const float*)d_in[7];
    float* out = (float*)d_out;

    cudaFuncSetAttribute(cde_kernel,
                         cudaFuncAttributeMaxDynamicSharedMemorySize, SMEM_BYTES);

    const int B    = in_sizes[0] / (T_N * IN_N);   // 1024
    const int grid = B / MC;                       // 128
    cde_kernel<<<grid, NTH, SMEM_BYTES>>>(coeffs, times, Wi, bi, Wf, bf, Wd, bd, out);
}

// round 11
// speedup vs baseline: 1.6396x; 1.0313x over previous
#include <cuda_runtime.h>
#include <cstdint>
#include <cstddef>

// Neural-CDE forward, R11 = R10 plus:
//  (a) packed-f32x2 TREE combine (depth 3, add.rn.f32x2) for both the
//      lipswish combine and the RK4 kv combine — shorter dependency tail,
//      half the add issues;
//  (b) packed-f32x2 projection: 2 output cols/thread (contiguous Wd pairs),
//      4-way K split — halves proj FMA-pipe cycles and LDS count;
//  (c) bd hoisted as a packed pair; proj scratch exchanged as u64.
// Config unchanged: 128 CTAs x 512 thr, MC=8, 8-way split-K, 4 cols/thread,
// fma.rn.f32x2 GEMM core, exact weight loads, cross-GEMM weight prefetch,
// group-local act-ready barriers.

#define T_N   128
#define IN_N  32
#define H_N   256
#define OUT_N 32
#define MC    8            // batch rows per CTA
#define BST   8            // activation buffer stride [dim][row]
#define NTH   512
#define NG    8            // split-K groups
#define NCT   64           // column-threads per group (4 cols each)
#define KSH   (H_N / NG)   // 32
#define KSI   (IN_N / NG)  // 4
#define RST   36           // reduction stride in floats (32 data + 4 pad)

#define BUF_FLOATS   (H_N * BST)            // 2048
#define RED_FLOATS   (NG * NCT * RST)       // 18432
#define SCR_FLOATS   768                    // proj partials: 3 quarters x 128 u64
#define SMEM_FLOATS  (2 * BUF_FLOATS + RED_FLOATS + SCR_FLOATS)
#define SMEM_BYTES   (SMEM_FLOATS * 4)      // 93184

typedef unsigned long long u64;

__device__ __forceinline__ u64 fma2(u64 a, u64 b, u64 c) {
    u64 d;
    asm("fma.rn.f32x2 %0, %1, %2, %3;" : "=l"(d) : "l"(a), "l"(b), "l"(c));
    return d;
}
__device__ __forceinline__ u64 add2(u64 a, u64 b) {
    u64 d;
    asm("add.rn.f32x2 %0, %1, %2;" : "=l"(d) : "l"(a), "l"(b));
    return d;
}
__device__ __forceinline__ u64 dup2(float x) {
    u64 d; unsigned int u = __float_as_uint(x);
    asm("mov.b64 %0, {%1, %2};" : "=l"(d) : "r"(u), "r"(u));
    return d;
}
__device__ __forceinline__ float2 unpk(u64 v) {
    unsigned int a, b;
    asm("mov.b64 {%0, %1}, %2;" : "=r"(a), "=r"(b) : "l"(v));
    return make_float2(__uint_as_float(a), __uint_as_float(b));
}
__device__ __forceinline__ u64 pk2(float x, float y) {
    u64 d; unsigned int a = __float_as_uint(x), b = __float_as_uint(y);
    asm("mov.b64 %0, {%1, %2};" : "=l"(d) : "r"(a), "r"(b));
    return d;
}
__device__ __forceinline__ float lipswish(float x) {
    return 0.909f * x / (1.0f + __expf(-x));
}
// 64-thread named barrier for split-K group kg (ids 1..8; 0 = __syncthreads).
__device__ __forceinline__ void gbar(int kg) {
    asm volatile("bar.sync %0, %1;" :: "r"(1 + kg), "r"(64) : "memory");
}

// Preload the first two 4-k-row weight blocks of a GEMM (guards compile out).
template <int KS>
__device__ __forceinline__ void wpre(const float* __restrict__ Wp,
                                     float4* __restrict__ wA,
                                     float4* __restrict__ wB)
{
#pragma unroll
    for (int j = 0; j < 4; j++) if (j < KS)     wA[j] = *(const float4*)(Wp + j * H_N);
#pragma unroll
    for (int j = 0; j < 4; j++) if (4 + j < KS) wB[j] = *(const float4*)(Wp + (4 + j) * H_N);
}

// Raw partial GEMM over KS k-rows, 4 columns, 8 rows. acc[c*4+p] packs rows
// (2p,2p+1) of local column c: p=0 -> ua.x, p=1 -> ua.y, p=2 -> ub.x,
// p=3 -> ub.y. Wp pre-offset to (koff, n0); bp pre-offset to koff. wA/wB hold
// the first two blocks (preloaded by caller before the previous barrier).
template <int KS>
__device__ __forceinline__ void gemmT4(const float* __restrict__ Wp,
                                       const float* __restrict__ bp,
                                       float4* __restrict__ wA,
                                       float4* __restrict__ wB,
                                       u64* __restrict__ acc)
{
#pragma unroll
    for (int i = 0; i < 16; i++) acc[i] = 0ull;

    ulonglong2 ua = *(const ulonglong2*)(bp);       // k-row 0: rows (0,1),(2,3)
    ulonglong2 ub = *(const ulonglong2*)(bp + 4);   //          rows (4,5),(6,7)

#pragma unroll
    for (int kb = 0; kb < KS; kb += 4) {
        float4 wN[4];
        const bool ldw = (kb + 8 < KS);
        if (ldw) {
#pragma unroll
            for (int j = 0; j < 4; j++) wN[j] = *(const float4*)(Wp + (kb + 8 + j) * H_N);
        }
#pragma unroll
        for (int j = 0; j < 4; j++) {
            if (kb + j >= KS) continue;                    // compile-time (KS=4 case)
            const int knext = kb + j + 1;
            ulonglong2 na, nb;
            const bool lda = (knext < KS);
            if (lda) {
                na = *(const ulonglong2*)(bp + knext * BST);
                nb = *(const ulonglong2*)(bp + knext * BST + 4);
            }
            u64 w0 = dup2(wA[j].x), w1 = dup2(wA[j].y);
            u64 w2 = dup2(wA[j].z), w3 = dup2(wA[j].w);
            acc[0]  = fma2(ua.x, w0, acc[0]);  acc[1]  = fma2(ua.y, w0, acc[1]);
            acc[2]  = fma2(ub.x, w0, acc[2]);  acc[3]  = fma2(ub.y, w0, acc[3]);
            acc[4]  = fma2(ua.x, w1, acc[4]);  acc[5]  = fma2(ua.y, w1, acc[5]);
            acc[6]  = fma2(ub.x, w1, acc[6]);  acc[7]  = fma2(ub.y, w1, acc[7]);
            acc[8]  = fma2(ua.x, w2, acc[8]);  acc[9]  = fma2(ua.y, w2, acc[9]);
            acc[10] = fma2(ub.x, w2, acc[10]); acc[11] = fma2(ub.y, w2, acc[11]);
            acc[12] = fma2(ua.x, w3, acc[12]); acc[13] = fma2(ua.y, w3, acc[13]);
            acc[14] = fma2(ub.x, w3, acc[14]); acc[15] = fma2(ub.y, w3, acc[15]);
            if (lda) { ua = na; ub = nb; }
        }
#pragma unroll
        for (int j = 0; j < 4; j++) wA[j] = wB[j];
        if (ldw) {
#pragma unroll
            for (int j = 0; j < 4; j++) wB[j] = wN[j];
        }
    }
}

// Deposit 32 raw floats (16 packed pairs) at redp: word layout c*8+m.
__device__ __forceinline__ void red_put(float* __restrict__ redp,
                                        const u64* __restrict__ acc)
{
#pragma unroll
    for (int c = 0; c < 4; c++) {
        *(ulonglong2*)(redp + c * 8)     = make_ulonglong2(acc[c * 4],     acc[c * 4 + 1]);
        *(ulonglong2*)(redp + c * 8 + 4) = make_ulonglong2(acc[c * 4 + 2], acc[c * 4 + 3]);
    }
}

// Sum the 8 group-partials for this thread's float4 via a packed-f32x2 tree
// (depth 3, 14 add2). Loads are LDS.128, conflict-free (verified per phase).
__device__ __forceinline__ float4 combine8(const float* __restrict__ red,
                                           int ct_e, int off)
{
    const float* p = red + ct_e * RST + off;
    ulonglong2 v0 = *(const ulonglong2*)(p);
    ulonglong2 v1 = *(const ulonglong2*)(p + 1 * NCT * RST);
    ulonglong2 v2 = *(const ulonglong2*)(p + 2 * NCT * RST);
    ulonglong2 v3 = *(const ulonglong2*)(p + 3 * NCT * RST);
    ulonglong2 v4 = *(const ulonglong2*)(p + 4 * NCT * RST);
    ulonglong2 v5 = *(const ulonglong2*)(p + 5 * NCT * RST);
    ulonglong2 v6 = *(const ulonglong2*)(p + 6 * NCT * RST);
    ulonglong2 v7 = *(const ulonglong2*)(p + 7 * NCT * RST);
    u64 ax = add2(add2(add2(v0.x, v1.x), add2(v2.x, v3.x)),
                  add2(add2(v4.x, v5.x), add2(v6.x, v7.x)));
    u64 ay = add2(add2(add2(v0.y, v1.y), add2(v2.y, v3.y)),
                  add2(add2(v4.y, v5.y), add2(v6.y, v7.y)));
    float2 lo = unpk(ax), hi = unpk(ay);
    return make_float4(lo.x, lo.y, hi.x, hi.y);
}

// Packed projection partial over one K-quarter: 2 output columns per thread.
// s2 = sum_{k in quarter} dup2(buf[k][r]) * Wd[k][2cp..2cp+1]  (+bd on q==0).
__device__ __forceinline__ u64 proj_part2(const float* __restrict__ buf,
                                          const float* __restrict__ Wd,
                                          u64 bd2, int q, int r, int cp)
{
    u64 s2 = (q == 0) ? bd2 : 0ull;
    const int k0 = q * (H_N / 4);
    const float* wp = Wd + 2 * cp;
#pragma unroll 8
    for (int kk = k0; kk < k0 + H_N / 4; kk++) {
        u64 w = *(const u64*)(wp + kk * OUT_N);
        s2 = fma2(dup2(buf[kk * BST + r]), w, s2);
    }
    return s2;
}

__global__ void __launch_bounds__(NTH, 1)
cde_kernel(const float* __restrict__ coeffs, const float* __restrict__ times,
           const float* __restrict__ Wi,     const float* __restrict__ bi,
           const float* __restrict__ Wf,     const float* __restrict__ bfb,
           const float* __restrict__ Wd,     const float* __restrict__ bd,
           float* __restrict__ out)
{
    extern __shared__ float smem[];
    float* bufA = smem;                                  // 2048 floats
    float* bufB = smem + BUF_FLOATS;                     // 2048 floats
    float* red  = smem + 2 * BUF_FLOATS;                 // 18432 floats
    u64*   scr  = (u64*)(smem + 2 * BUF_FLOATS + RED_FLOATS);  // 3*128 u64

    const int tid   = threadIdx.x;
    const int kg    = tid >> 6;                 // split-K group 0..7
    const int ct    = tid & 63;                 // column-thread in group
    const int n0    = ct * 4;
    const int bbase = blockIdx.x * MC;

    // combine/update mapping: thread owns column n_e, rows m0..m0+3.
    const int ct_e = tid >> 3;
    const int sub  = tid & 7;
    const int c_e  = sub >> 1;
    const int m0   = (sub & 1) * 4;
    const int n_e  = ct_e * 4 + c_e;
    const int off  = c_e * 8 + m0;

    // projection mapping: 128 units (8 rows x 16 col-pairs) x 4 K-quarters
    const int p_q    = tid >> 7;                // K-quarter 0..3
    const int p_unit = tid & 127;
    const int p_r    = p_unit >> 4;             // batch row 0..7
    const int p_cp   = p_unit & 15;             // col-pair 0..15

    float* redp = red + (kg * NCT + ct) * RST;
    u64 acc[16];
    float4 wA[4], wB[4];

    // loop-invariant scalars hoisted off the combine critical path
    const float bias0 = bfb[0 * H_N + n_e];
    const float bias1 = bfb[1 * H_N + n_e];
    const float bias2 = bfb[2 * H_N + n_e];
    const float bias3 = bfb[3 * H_N + n_e];
    const u64   bd2   = *(const u64*)(bd + 2 * p_cp);

    // per-thread weight base for the hidden layers
    const size_t HH = (size_t)H_N * H_N;
    const float* W0 = Wf + (size_t)kg * KSH * H_N + n0;
    const int kact  = kg * KSH * BST;           // act offset for hidden GEMMs

    // hoisted output base for this thread's projection writes
    float* outp = out + (size_t)(bbase + p_r) * T_N * OUT_N + 2 * p_cp;

    // ---- stage coeffs[:,0,:] -> bufA[k][m] ----
    if (tid < 256) {
        int m = tid >> 5, kk = tid & 31;
        bufA[kk * BST + m] = coeffs[(size_t)(bbase + m) * T_N * IN_N + kk];
    }

    // preload init-GEMM weights (KSI=4: one block) while staging lands
    wpre<KSI>(Wi + (size_t)kg * KSI * H_N + n0, wA, wB);
    __syncthreads();

    // ---- y0 = coeffs0 @ Wi + bi ----
    float y[4], ksum[4];
    gemmT4<KSI>(Wi + (size_t)kg * KSI * H_N + n0, bufA + kg * KSI * BST, wA, wB, acc);
    red_put(redp, acc);
    wpre<KSH>(W0, wA, wB);                      // prefetch layer-0 weights
    __syncthreads();
    {
        float4 v = combine8(red, ct_e, off);
        float bb = bi[n_e];
        y[0] = v.x + bb; y[1] = v.y + bb; y[2] = v.z + bb; y[3] = v.w + bb;
        *(float4*)(bufA + n_e * BST + m0) = make_float4(y[0], y[1], y[2], y[3]);
    }
    __syncthreads();            // full: next proj (st0/l0) reads ALL columns

    // ---- time loop; proj of y_t folded into stage-0/layer-0 of step t ----
#pragma unroll 1
    for (int t = 0; t < T_N - 1; t++) {
        const float dt = times[t + 1] - times[t];

#pragma unroll 1
        for (int st = 0; st < 4; st++) {
            float* in = bufA; float* ob = bufB;
            u64 ps2 = 0ull;
#pragma unroll 1
            for (int l = 0; l < 3; l++) {
                if (st == 0 && l == 0) {
                    // projection partial of y_t (bufA stable through this GEMM)
                    ps2 = proj_part2(bufA, Wd, bd2, p_q, p_r, p_cp);
                    if (p_q) scr[(p_q - 1) * 128 + p_unit] = ps2;
                }
                gemmT4<KSH>(W0 + l * HH, in + kact, wA, wB, acc);
                red_put(redp, acc);
                wpre<KSH>(W0 + (l + 1) * HH, wA, wB);   // prefetch next layer
                __syncthreads();     // full: deposits cross all groups (+scr)
                if (st == 0 && l == 0 && p_q == 0) {
                    u64 s = add2(add2(ps2, scr[p_unit]),
                                 add2(scr[128 + p_unit], scr[256 + p_unit]));
                    *(float2*)(outp + (size_t)t * OUT_N) = unpk(s);
                }
                float4 v = combine8(red, ct_e, off);
                float bb = (l == 0) ? bias0 : (l == 1) ? bias1 : bias2;
                v.x = lipswish(v.x + bb); v.y = lipswish(v.y + bb);
                v.z = lipswish(v.z + bb); v.w = lipswish(v.w + bb);
                *(float4*)(ob + n_e * BST + m0) = v;
                gbar(kg);            // group-local: own GEMM reads own columns
                float* tmp = in; in = ob; ob = tmp;
            }
            gemmT4<KSH>(W0 + 3 * HH, in + kact, wA, wB, acc);
            red_put(redp, acc);
            wpre<KSH>(W0, wA, wB);                      // prefetch next stage L0
            __syncthreads();         // full: deposits cross all groups
            float4 kv = combine8(red, ct_e, off);
            kv.x += bias3; kv.y += bias3; kv.z += bias3; kv.w += bias3;
            float k4[4] = {kv.x, kv.y, kv.z, kv.w};
            float s4[4];
            if (st == 0) {
#pragma unroll
                for (int i = 0; i < 4; i++) { ksum[i] = k4[i]; s4[i] = fmaf(0.5f * dt, k4[i], y[i]); }
            } else if (st == 1) {
#pragma unroll
                for (int i = 0; i < 4; i++) { ksum[i] = fmaf(2.f, k4[i], ksum[i]); s4[i] = fmaf(0.5f * dt, k4[i], y[i]); }
            } else if (st == 2) {
#pragma unroll
                for (int i = 0; i < 4; i++) { ksum[i] = fmaf(2.f, k4[i], ksum[i]); s4[i] = fmaf(dt, k4[i], y[i]); }
            } else {
#pragma unroll
                for (int i = 0; i < 4; i++) { ksum[i] += k4[i]; y[i] = fmaf(dt * (1.f / 6.f), ksum[i], y[i]); s4[i] = y[i]; }
            }
            *(float4*)(bufA + n_e * BST + m0) = make_float4(s4[0], s4[1], s4[2], s4[3]);
            if (st < 3) gbar(kg);    // group-local: next stage L0 reads own cols
            else        __syncthreads();   // full: st0/l0 proj reads ALL columns
        }
    }

    // ---- final projection of y_{T-1} ----
    {
        u64 ps2 = proj_part2(bufA, Wd, bd2, p_q, p_r, p_cp);
        if (p_q) scr[(p_q - 1) * 128 + p_unit] = ps2;
        __syncthreads();
        if (p_q == 0) {
            u64 s = add2(add2(ps2, scr[p_unit]),
                         add2(scr[128 + p_unit], scr[256 + p_unit]));
            *(float2*)(outp + (size_t)(T_N - 1) * OUT_N) = unpk(s);
        }
    }
}

extern "C" void kernel_launch(void* const* d_in, const int* in_sizes, int n_in,
                              void* d_out, int out_size)
{
    const float* coeffs = (const float*)d_in[0];
    const float* times  = (const float*)d_in[1];
    const float* Wi     = (const float*)d_in[2];
    const float* bi     = (const float*)d_in[3];
    const float* Wf     = (const float*)d_in[4];
    const float* bf     = (const float*)d_in[5];
    const float* Wd     = (const float*)d_in[6];
    const float* bd     = (const float*)d_in[7];
    float* out = (float*)d_out;

    cudaFuncSetAttribute(cde_kernel,
                         cudaFuncAttributeMaxDynamicSharedMemorySize, SMEM_BYTES);

    const int B    = in_sizes[0] / (T_N * IN_N);   // 1024
    const int grid = B / MC;                       // 128
    cde_kernel<<<grid, NTH, SMEM_BYTES>>>(coeffs, times, Wi, bi, Wf, bf, Wd, bd, out);
}